// round 11
// baseline (speedup 1.0000x reference)
#include <cuda_runtime.h>
#include <math.h>

#define T_DATA 200000
#define SUB_NO 20
#define T_NO   200
#define E_NO   400
#define I_NO   100
#define N_BASIS 20

typedef unsigned long long ull;

// ---------------- packed f32x2 helpers --------------------------------------
__device__ __forceinline__ ull fma2(ull a, ull b, ull c) {
    ull d;
    asm("fma.rn.f32x2 %0, %1, %2, %3;" : "=l"(d) : "l"(a), "l"(b), "l"(c));
    return d;
}
__device__ __forceinline__ ull pk2(float lo, float hi) {
    ull r;
    asm("mov.b64 %0, {%1, %2};" : "=l"(r) : "f"(lo), "f"(hi));
    return r;
}
__device__ __forceinline__ float tanh_ap(float x) {
    float y;
    asm("tanh.approx.f32 %0, %1;" : "=f"(y) : "f"(x));
    return y;
}

// ---------------- scratch (device globals; no allocations allowed) ----------
__device__ float  g_syn_e [SUB_NO * T_DATA];
__device__ float  g_syn_i [SUB_NO * T_DATA];
__device__ float  g_syn_ns[SUB_NO * T_DATA];   // from IIR
__device__ float  g_syn_s [SUB_NO * T_DATA];   // from FIR
__device__ float  g_hist_ns[T_DATA];
__device__ float  g_hist_s [T_DATA];
__device__ ull    g_kds[SUB_NO * T_NO * 2];    // duplicated (k,k) pairs {e_s, i_s}
__device__ ull    g_hd[T_NO * 2];              // duplicated hist kernels {ns, s}
__device__ int    g_e_asn[E_NO];
__device__ int    g_i_asn[I_NO];

// ---------------- K1: filters, assignments (multi-block) --------------------
__global__ void setup_kernel(const float* __restrict__ Wns,
                             const float* __restrict__ Tau,
                             const float* __restrict__ Delta,
                             const float* __restrict__ Wsyn_s,
                             const float* __restrict__ hist_s_w,
                             const float* __restrict__ hist_ns_w,
                             const float* __restrict__ C_syn_e,
                             const float* __restrict__ C_syn_i,
                             float* __restrict__ out_filters)
{
    const float PI_F = 3.14159265358979323846f;
    const int gtid = blockIdx.x * blockDim.x + threadIdx.x;
    const int gstr = gridDim.x * blockDim.x;

    for (int idx = gtid; idx < SUB_NO * T_NO; idx += gstr) {
        int s = idx / T_NO;
        int j = idx - s * T_NO;
        float t = (float)j;
        float tau_e = Tau[s*2+0] * Tau[s*2+0];
        float tau_i = Tau[s*2+1] * Tau[s*2+1];
        float te = fmaxf(t - Delta[s*2+0], 0.0f) / tau_e;
        float ti = fmaxf(t - Delta[s*2+1], 0.0f) / tau_i;
        float we0 = Wns[s*2+0], wi0 = Wns[s*2+1];
        float ke =  te * expf(-te) * we0 * we0;
        float ki = -ti * expf(-ti) * wi0 * wi0;

        float raw = 5.0f * logf(t + 1.0f);
        float se = 0.0f, si = 0.0f;
        #pragma unroll
        for (int b = 0; b < N_BASIS; b++) {
            float phi = 1.57079632679489662f * (float)b;
            float v = 0.0f;
            if (raw >= phi - PI_F && raw <= phi + PI_F)
                v = 0.5f * cosf(raw - phi) + 0.5f;
            float wse = Wsyn_s[(s*N_BASIS + b)*2 + 0];
            float wsi = Wsyn_s[(s*N_BASIS + b)*2 + 1];
            se += wse * wse * v;
            si += wsi * wsi * v;
        }
        si = -si;

        g_kds[idx*2 + 0] = pk2(se, se);
        g_kds[idx*2 + 1] = pk2(si, si);
        out_filters[0*SUB_NO*T_NO + idx] = ke;
        out_filters[1*SUB_NO*T_NO + idx] = ki;
        out_filters[2*SUB_NO*T_NO + idx] = se;
        out_filters[3*SUB_NO*T_NO + idx] = si;
    }

    for (int j = gtid; j < T_NO; j += gstr) {
        float raw = 5.0f * logf((float)j + 1.0f);
        float hs = 0.0f, hns = 0.0f;
        #pragma unroll
        for (int b = 0; b < N_BASIS; b++) {
            float phi = 1.57079632679489662f * (float)b;
            float v = 0.0f;
            if (raw >= phi - PI_F && raw <= phi + PI_F)
                v = 0.5f * cosf(raw - phi) + 0.5f;
            hs  += hist_s_w[b]  * v;
            hns += hist_ns_w[b] * v;
        }
        g_hd[j*2 + 0] = pk2(hns, hns);
        g_hd[j*2 + 1] = pk2(hs, hs);
        out_filters[4*SUB_NO*T_NO + j]        = hns;  // row 80
        out_filters[4*SUB_NO*T_NO + T_NO + j] = hs;   // row 81
    }

    for (int e = gtid; e < E_NO; e += gstr) {
        int a = 0;
        for (int s = 0; s < SUB_NO; s++)
            if (C_syn_e[s*E_NO + e] != 0.0f) a = s;
        g_e_asn[e] = a;
    }
    for (int i2 = gtid; i2 < I_NO; i2 += gstr) {
        int a = 0;
        for (int s = 0; s < SUB_NO; s++)
            if (C_syn_i[s*I_NO + i2] != 0.0f) a = s;
        g_i_asn[i2] = a;
    }
}

// ---------------- K2: spike binning  syn = S @ C.T (one-hot), float4 --------
#define BT   32
#define BTH  256
__global__ __launch_bounds__(BTH) void bin_kernel(const float4* __restrict__ Se4,
                                                  const float4* __restrict__ Si4)
{
    __shared__ float be[BT * SUB_NO];
    __shared__ float bi[BT * SUB_NO];
    __shared__ int   ea[E_NO];
    __shared__ int   ia[I_NO];
    const int tid = threadIdx.x;
    const int t0  = blockIdx.x * BT;

    for (int i = tid; i < BT * SUB_NO; i += BTH) { be[i] = 0.0f; bi[i] = 0.0f; }
    for (int i = tid; i < E_NO; i += BTH) ea[i] = g_e_asn[i];
    for (int i = tid; i < I_NO; i += BTH) ia[i] = g_i_asn[i];
    __syncthreads();

    for (int idx = tid; idx < BT * (E_NO/4); idx += BTH) {
        int r = idx / (E_NO/4);
        int c = idx - r * (E_NO/4);
        int t = t0 + r;
        if (t < T_DATA) {
            float4 v = Se4[(size_t)t * (E_NO/4) + c];
            int e0 = c * 4;
            if (v.x != 0.0f) atomicAdd(&be[r * SUB_NO + ea[e0+0]], v.x);
            if (v.y != 0.0f) atomicAdd(&be[r * SUB_NO + ea[e0+1]], v.y);
            if (v.z != 0.0f) atomicAdd(&be[r * SUB_NO + ea[e0+2]], v.z);
            if (v.w != 0.0f) atomicAdd(&be[r * SUB_NO + ea[e0+3]], v.w);
        }
    }
    for (int idx = tid; idx < BT * (I_NO/4); idx += BTH) {
        int r = idx / (I_NO/4);
        int c = idx - r * (I_NO/4);
        int t = t0 + r;
        if (t < T_DATA) {
            float4 v = Si4[(size_t)t * (I_NO/4) + c];
            int i0 = c * 4;
            if (v.x != 0.0f) atomicAdd(&bi[r * SUB_NO + ia[i0+0]], v.x);
            if (v.y != 0.0f) atomicAdd(&bi[r * SUB_NO + ia[i0+1]], v.y);
            if (v.z != 0.0f) atomicAdd(&bi[r * SUB_NO + ia[i0+2]], v.z);
            if (v.w != 0.0f) atomicAdd(&bi[r * SUB_NO + ia[i0+3]], v.w);
        }
    }
    __syncthreads();

    for (int idx = tid; idx < BT * SUB_NO; idx += BTH) {
        int s  = idx / BT;
        int tl = idx - s * BT;
        int t  = t0 + tl;
        if (t < T_DATA) {
            g_syn_e[(size_t)s * T_DATA + t] = be[tl * SUB_NO + s];
            g_syn_i[(size_t)s * T_DATA + t] = bi[tl * SUB_NO + s];
        }
    }
}

// ---------------- K3: IIR for ns (alpha) filters ----------------------------
#define IL    391      // outputs per chunk
#define ICH   512      // chunks per sub (512*391 >= T_DATA)
#define IBC   64       // chunks (= threads) per block
#define IWARM 200
__global__ __launch_bounds__(IBC) void iir_kernel(const float* __restrict__ Wns,
                                                  const float* __restrict__ Tau)
{
    const int s   = blockIdx.y;
    const int cg  = blockIdx.x * IBC;          // first chunk of this block
    const int tid = threadIdx.x;

    float tau_e = Tau[s*2+0] * Tau[s*2+0];
    float tau_i = Tau[s*2+1] * Tau[s*2+1];
    float a_e = 1.0f / tau_e,  a_i = 1.0f / tau_i;
    float r_e = expf(-a_e),    r_i = expf(-a_i);
    float we0 = Wns[s*2+0],    wi0 = Wns[s*2+1];
    float sc_e =  we0 * we0 * a_e;
    float sc_i = -wi0 * wi0 * a_i;

    __shared__ float xe[IBC][33];
    __shared__ float xi[IBC][33];
    __shared__ float yo[IBC][33];

    const float* pe = g_syn_e + (size_t)s * T_DATA;
    const float* pi = g_syn_i + (size_t)s * T_DATA;
    float* po = g_syn_ns + (size_t)s * T_DATA;

    float ue = 0.0f, ve = 0.0f, ui = 0.0f, vi = 0.0f;

    for (int i0 = 0; i0 < 608; i0 += 32) {      // 19 tiles cover 591 steps
        for (int flat = tid; flat < IBC * 32; flat += IBC) {
            int c = flat >> 5, p = flat & 31;
            long t = (long)(cg + c) * IL - IWARM + i0 + p;
            bool ok = (t >= 0) && (t < T_DATA);
            xe[c][p] = ok ? pe[t] : 0.0f;
            xi[c][p] = ok ? pi[t] : 0.0f;
        }
        __syncthreads();

        #pragma unroll
        for (int p = 0; p < 32; p++) {
            float xev = xe[tid][p], xiv = xi[tid][p];
            ve = r_e * (ve + ue);  ue = fmaf(r_e, ue, xev);
            vi = r_i * (vi + ui);  ui = fmaf(r_i, ui, xiv);
            yo[tid][p] = sc_e * ve + sc_i * vi;
        }
        __syncthreads();

        for (int flat = tid; flat < IBC * 32; flat += IBC) {
            int c = flat >> 5, p = flat & 31;
            int io = i0 + p - IWARM;
            long t = (long)(cg + c) * IL + io;
            if (io >= 0 && io < IL && t < T_DATA)
                po[t] = yo[c][p];
        }
    }
}

// ---------------- K4: FIR conv (s kernels, packed f32x2) + hist -------------
// Pair-permuted smem layout: logical pair q lives at (q&7)*PG + (q>>3).
// Mainloop pair indices are tid*8 + m with warp-uniform m, so the stored
// address is (m&7)*PG + (m>>3) + tid -> lane stride 1 pair (8B) ->
// conflict-free LDS.64 for initial window loads AND all refills.
// NOTE (round-10 bug): even arrays (xe/xi) use m = 100+p / 100-jj; odd
// (+1-shifted) arrays (xes/xis) use m = 99+p / 99-jj. They differ by one.
#define CT   2048    // timesteps per block
#define CTH  128     // threads per block (16 outputs = 8 pairs each)
#define NP   8       // pairs per thread
#define XSZ  (CT + T_NO)       // 2248 floats
#define PG   141               // pair groups: 8*141 = 1128 >= 1124 pairs

__device__ __forceinline__ int pidx(int q) { return (q & 7) * PG + (q >> 3); }
__device__ __forceinline__ int paddr(int m, int tid) {
    return (m & 7) * PG + (m >> 3) + tid;
}

__global__ __launch_bounds__(CTH) void conv_kernel(const float* __restrict__ Z)
{
    const int s  = blockIdx.y;
    const int t0 = blockIdx.x * CT;
    __shared__ ull xe [8 * PG];
    __shared__ ull xes[8 * PG];
    __shared__ ull xi [8 * PG];
    __shared__ ull xis[8 * PG];
    __shared__ ull kd[T_NO * 2];
    float* xeF  = (float*)xe;
    float* xesF = (float*)xes;
    float* xiF  = (float*)xi;
    float* xisF = (float*)xis;
    const int tid = threadIdx.x;

    if (s < SUB_NO) {
        const float* pe = g_syn_e + (size_t)s * T_DATA;
        const float* pi = g_syn_i + (size_t)s * T_DATA;
        for (int i = tid; i < XSZ; i += CTH) {
            int t  = t0 - T_NO + i;
            int t1 = t + 1;
            bool ok0 = (t  >= 0) && (t  < T_DATA);
            bool ok1 = (t1 >= 0) && (t1 < T_DATA);
            int fi = pidx(i >> 1) * 2 + (i & 1);
            xeF [fi] = ok0 ? pe[t]  : 0.0f;
            xiF [fi] = ok0 ? pi[t]  : 0.0f;
            xesF[fi] = ok1 ? pe[t1] : 0.0f;
            xisF[fi] = ok1 ? pi[t1] : 0.0f;
        }
        for (int i = tid; i < T_NO * 2; i += CTH)
            kd[i] = g_kds[(size_t)s * T_NO * 2 + i];
        __syncthreads();

        ull WEe[NP], WOe[NP], WEi[NP], WOi[NP], as2[NP];
        #pragma unroll
        for (int p = 0; p < NP; p++) {
            int ae = paddr(100 + p, tid);        // even pairs: x[.. -2jj]
            int ao = paddr(99 + p,  tid);        // odd pairs (+1-shifted array)
            WEe[p] = xe [ae]; WOe[p] = xes[ao];
            WEi[p] = xi [ae]; WOi[p] = xis[ao];
            as2[p] = 0ULL;
        }

        auto phases = [&](int jj) {
            ull k0s = kd[(2*jj)*2+0], k0t = kd[(2*jj)*2+1];
            #pragma unroll
            for (int p = 0; p < NP; p++) {
                as2[p] = fma2(k0s, WEe[p], as2[p]);
                as2[p] = fma2(k0t, WEi[p], as2[p]);
            }
            ull k1s = kd[(2*jj+1)*2+0], k1t = kd[(2*jj+1)*2+1];
            #pragma unroll
            for (int p = 0; p < NP; p++) {
                as2[p] = fma2(k1s, WOe[p], as2[p]);
                as2[p] = fma2(k1t, WOi[p], as2[p]);
            }
        };
        auto rot = [&](int jj) {
            #pragma unroll
            for (int p = NP - 1; p > 0; p--) {
                WEe[p] = WEe[p-1]; WOe[p] = WOe[p-1];
                WEi[p] = WEi[p-1]; WOi[p] = WOi[p-1];
            }
            int ae = paddr(100 - jj, tid);
            int ao = paddr(99 - jj,  tid);
            WEe[0] = xe [ae]; WOe[0] = xes[ao];
            WEi[0] = xi [ae]; WOi[0] = xis[ao];
        };

        phases(0);
        #pragma unroll 8
        for (int jj = 1; jj < 97; jj++) { rot(jj); phases(jj); }   // 96 iters
        #pragma unroll
        for (int jj = 97; jj < 100; jj++) { rot(jj); phases(jj); } // tail

        float* os = g_syn_s + (size_t)s * T_DATA + t0 + tid * 16;
        #pragma unroll
        for (int p = 0; p < NP; p++)
            if (t0 + tid * 16 + 2*p < T_DATA) *(ull*)(os + 2*p) = as2[p];
    } else {
        // ---- spike-history slice: hist[t] = sum_j k[j] * Z[t-1-j] ----
        for (int i = tid; i < XSZ; i += CTH) {
            int t  = t0 - T_NO + i - 1;
            int t1 = t + 1;
            int fi = pidx(i >> 1) * 2 + (i & 1);
            xeF [fi] = (t  >= 0 && t  < T_DATA) ? Z[t]  : 0.0f;
            xesF[fi] = (t1 >= 0 && t1 < T_DATA) ? Z[t1] : 0.0f;
        }
        for (int i = tid; i < T_NO * 2; i += CTH) kd[i] = g_hd[i];
        __syncthreads();

        ull WE[NP], WO[NP], hn[NP], hs[NP];
        #pragma unroll
        for (int p = 0; p < NP; p++) {
            int ae = paddr(100 + p, tid);
            int ao = paddr(99 + p,  tid);
            WE[p] = xe[ae]; WO[p] = xes[ao];
            hn[p] = 0ULL; hs[p] = 0ULL;
        }
        auto phases = [&](int jj) {
            ull k0n = kd[(2*jj)*2+0], k0s = kd[(2*jj)*2+1];
            #pragma unroll
            for (int p = 0; p < NP; p++) {
                hn[p] = fma2(k0n, WE[p], hn[p]);
                hs[p] = fma2(k0s, WE[p], hs[p]);
            }
            ull k1n = kd[(2*jj+1)*2+0], k1s = kd[(2*jj+1)*2+1];
            #pragma unroll
            for (int p = 0; p < NP; p++) {
                hn[p] = fma2(k1n, WO[p], hn[p]);
                hs[p] = fma2(k1s, WO[p], hs[p]);
            }
        };
        auto rot = [&](int jj) {
            #pragma unroll
            for (int p = NP - 1; p > 0; p--) { WE[p] = WE[p-1]; WO[p] = WO[p-1]; }
            int ae = paddr(100 - jj, tid);
            int ao = paddr(99 - jj,  tid);
            WE[0] = xe[ae]; WO[0] = xes[ao];
        };
        phases(0);
        #pragma unroll 8
        for (int jj = 1; jj < 97; jj++) { rot(jj); phases(jj); }
        #pragma unroll
        for (int jj = 97; jj < 100; jj++) { rot(jj); phases(jj); }

        #pragma unroll
        for (int p = 0; p < NP; p++) {
            int t = t0 + tid * 16 + 2*p;
            if (t < T_DATA) {
                *(ull*)(g_hist_ns + t) = hn[p];
                *(ull*)(g_hist_s  + t) = hs[p];
            }
        }
    }
}

// ---------------- K5: leaf-to-root binary tree + outputs (2 t / thread) -----
#define TTH 128
__global__ __launch_bounds__(TTH) void tree_kernel(
    const float* __restrict__ Theta_ns, const float* __restrict__ Theta_s,
    const float* __restrict__ W_sub_ns, const float* __restrict__ W_sub_s,
    const float* __restrict__ V_o, float* __restrict__ out)
{
    const int gt = blockIdx.x * TTH + threadIdx.x;        // float2 index
    if (gt * 2 >= T_DATA) return;

    float2 vs[SUB_NO], vn[SUB_NO];
    #pragma unroll
    for (int s2 = 0; s2 < SUB_NO; s2++) {
        vs[s2] = ((const float2*)(g_syn_s  + (size_t)s2 * T_DATA))[gt];
        vn[s2] = ((const float2*)(g_syn_ns + (size_t)s2 * T_DATA))[gt];
    }

    #pragma unroll
    for (int idx = SUB_NO - 1; idx >= 1; idx--) {
        const int p = (idx - 1) >> 1;
        float w = __ldg(&W_sub_s[idx]);  float w2s = w * w;
        w = __ldg(&W_sub_ns[idx]);       float w2n = w * w;
        float ts = __ldg(&Theta_s[idx]), tn = __ldg(&Theta_ns[idx]);
        vs[p].x += tanh_ap(vs[idx].x + ts) * w2s;
        vs[p].y += tanh_ap(vs[idx].y + ts) * w2s;
        vn[p].x += tanh_ap(vn[idx].x + tn) * w2n;
        vn[p].y += tanh_ap(vn[idx].y + tn) * w2n;
    }

    float2 hsv = ((const float2*)g_hist_s)[gt];
    float2 hnv = ((const float2*)g_hist_ns)[gt];
    float ts0 = __ldg(&Theta_s[0]), tn0 = __ldg(&Theta_ns[0]);
    float w0 = __ldg(&W_sub_ns[0]); float wn20 = w0 * w0;
    float vo = __ldg(&V_o[0]);

    float2 fv, fz;
    fz.x = 0.5f * tanh_ap(0.5f * (hsv.x + vs[0].x + ts0)) + 0.5f;
    fz.y = 0.5f * tanh_ap(0.5f * (hsv.y + vs[0].y + ts0)) + 0.5f;
    fv.x = tanh_ap(hnv.x + vn[0].x + tn0) * wn20 + vo;
    fv.y = tanh_ap(hnv.y + vn[0].y + tn0) * wn20 + vo;

    ((float2*)out)[gt] = fv;                       // final_V
    ((float2*)(out + T_DATA))[gt] = fz;            // final_Z
}

// ---------------- launch ----------------------------------------------------
extern "C" void kernel_launch(void* const* d_in, const int* in_sizes, int n_in,
                              void* d_out, int out_size)
{
    const float* S_e      = (const float*)d_in[0];
    const float* S_i      = (const float*)d_in[1];
    const float* Z        = (const float*)d_in[2];
    const float* C_syn_e  = (const float*)d_in[4];
    const float* C_syn_i  = (const float*)d_in[5];
    const float* W_syn_ns = (const float*)d_in[6];
    const float* Tau      = (const float*)d_in[7];
    const float* Delta    = (const float*)d_in[8];
    const float* W_syn_s  = (const float*)d_in[9];
    const float* W_sub_ns = (const float*)d_in[10];
    const float* W_sub_s  = (const float*)d_in[11];
    const float* V_o      = (const float*)d_in[12];
    const float* Theta_ns = (const float*)d_in[13];
    const float* Theta_s  = (const float*)d_in[14];
    const float* hist_s_w = (const float*)d_in[15];
    const float* hist_ns_w= (const float*)d_in[16];

    float* out = (float*)d_out;
    float* out_filters = out + 2 * T_DATA;   // final_V | final_Z | filters(82x200)

    setup_kernel<<<40, 128>>>(W_syn_ns, Tau, Delta, W_syn_s, hist_s_w, hist_ns_w,
                              C_syn_e, C_syn_i, out_filters);

    bin_kernel<<<(T_DATA + BT - 1) / BT, BTH>>>((const float4*)S_e,
                                                (const float4*)S_i);

    iir_kernel<<<dim3(ICH / IBC, SUB_NO), IBC>>>(W_syn_ns, Tau);

    dim3 cgrid((T_DATA + CT - 1) / CT, SUB_NO + 1);  // y==SUB_NO -> hist slice
    conv_kernel<<<cgrid, CTH>>>(Z);

    tree_kernel<<<(T_DATA / 2 + TTH - 1) / TTH, TTH>>>(Theta_ns, Theta_s,
                                                       W_sub_ns, W_sub_s, V_o, out);
}

// round 14
// speedup vs baseline: 1.3313x; 1.3313x over previous
#include <cuda_runtime.h>
#include <math.h>

#define T_DATA 200000
#define SUB_NO 20
#define T_NO   200
#define E_NO   400
#define I_NO   100
#define N_BASIS 20

typedef unsigned long long ull;

// ---------------- packed f32x2 helpers --------------------------------------
__device__ __forceinline__ ull fma2(ull a, ull b, ull c) {
    ull d;
    asm("fma.rn.f32x2 %0, %1, %2, %3;" : "=l"(d) : "l"(a), "l"(b), "l"(c));
    return d;
}
__device__ __forceinline__ ull pk2(float lo, float hi) {
    ull r;
    asm("mov.b64 %0, {%1, %2};" : "=l"(r) : "f"(lo), "f"(hi));
    return r;
}
// result: lo32 = hi32(a), hi32 = lo32(b)  (odd-window construction)
__device__ __forceinline__ ull mix_hl(ull a, ull b) {
    unsigned int ah = (unsigned int)(a >> 32);
    unsigned int bl = (unsigned int)b;
    ull r;
    asm("mov.b64 %0, {%1, %2};" : "=l"(r) : "r"(ah), "r"(bl));
    return r;
}
__device__ __forceinline__ float tanh_ap(float x) {
    float y;
    asm("tanh.approx.f32 %0, %1;" : "=f"(y) : "f"(x));
    return y;
}

// ---------------- scratch (device globals; no allocations allowed) ----------
__device__ float  g_syn_e [SUB_NO * T_DATA];
__device__ float  g_syn_i [SUB_NO * T_DATA];
__device__ float  g_syn_ns[SUB_NO * T_DATA];   // from IIR
__device__ float  g_syn_s [SUB_NO * T_DATA];   // from FIR
__device__ float  g_hist_ns[T_DATA];
__device__ float  g_hist_s [T_DATA];
__device__ ull    g_kds[SUB_NO * T_NO * 2];    // duplicated (k,k) pairs {e_s, i_s}
__device__ ull    g_hd[T_NO * 2];              // duplicated hist kernels {ns, s}
__device__ int    g_e_asn[E_NO];
__device__ int    g_i_asn[I_NO];

// ---------------- K1: filters, assignments (multi-block) --------------------
__global__ void setup_kernel(const float* __restrict__ Wns,
                             const float* __restrict__ Tau,
                             const float* __restrict__ Delta,
                             const float* __restrict__ Wsyn_s,
                             const float* __restrict__ hist_s_w,
                             const float* __restrict__ hist_ns_w,
                             const float* __restrict__ C_syn_e,
                             const float* __restrict__ C_syn_i,
                             float* __restrict__ out_filters)
{
    const float PI_F = 3.14159265358979323846f;
    const int gtid = blockIdx.x * blockDim.x + threadIdx.x;
    const int gstr = gridDim.x * blockDim.x;

    for (int idx = gtid; idx < SUB_NO * T_NO; idx += gstr) {
        int s = idx / T_NO;
        int j = idx - s * T_NO;
        float t = (float)j;
        float tau_e = Tau[s*2+0] * Tau[s*2+0];
        float tau_i = Tau[s*2+1] * Tau[s*2+1];
        float te = fmaxf(t - Delta[s*2+0], 0.0f) / tau_e;
        float ti = fmaxf(t - Delta[s*2+1], 0.0f) / tau_i;
        float we0 = Wns[s*2+0], wi0 = Wns[s*2+1];
        float ke =  te * expf(-te) * we0 * we0;
        float ki = -ti * expf(-ti) * wi0 * wi0;

        float raw = 5.0f * logf(t + 1.0f);
        float se = 0.0f, si = 0.0f;
        #pragma unroll
        for (int b = 0; b < N_BASIS; b++) {
            float phi = 1.57079632679489662f * (float)b;
            float v = 0.0f;
            if (raw >= phi - PI_F && raw <= phi + PI_F)
                v = 0.5f * cosf(raw - phi) + 0.5f;
            float wse = Wsyn_s[(s*N_BASIS + b)*2 + 0];
            float wsi = Wsyn_s[(s*N_BASIS + b)*2 + 1];
            se += wse * wse * v;
            si += wsi * wsi * v;
        }
        si = -si;

        g_kds[idx*2 + 0] = pk2(se, se);
        g_kds[idx*2 + 1] = pk2(si, si);
        out_filters[0*SUB_NO*T_NO + idx] = ke;
        out_filters[1*SUB_NO*T_NO + idx] = ki;
        out_filters[2*SUB_NO*T_NO + idx] = se;
        out_filters[3*SUB_NO*T_NO + idx] = si;
    }

    for (int j = gtid; j < T_NO; j += gstr) {
        float raw = 5.0f * logf((float)j + 1.0f);
        float hs = 0.0f, hns = 0.0f;
        #pragma unroll
        for (int b = 0; b < N_BASIS; b++) {
            float phi = 1.57079632679489662f * (float)b;
            float v = 0.0f;
            if (raw >= phi - PI_F && raw <= phi + PI_F)
                v = 0.5f * cosf(raw - phi) + 0.5f;
            hs  += hist_s_w[b]  * v;
            hns += hist_ns_w[b] * v;
        }
        g_hd[j*2 + 0] = pk2(hns, hns);
        g_hd[j*2 + 1] = pk2(hs, hs);
        out_filters[4*SUB_NO*T_NO + j]        = hns;  // row 80
        out_filters[4*SUB_NO*T_NO + T_NO + j] = hs;   // row 81
    }

    for (int e = gtid; e < E_NO; e += gstr) {
        int a = 0;
        for (int s = 0; s < SUB_NO; s++)
            if (C_syn_e[s*E_NO + e] != 0.0f) a = s;
        g_e_asn[e] = a;
    }
    for (int i2 = gtid; i2 < I_NO; i2 += gstr) {
        int a = 0;
        for (int s = 0; s < SUB_NO; s++)
            if (C_syn_i[s*I_NO + i2] != 0.0f) a = s;
        g_i_asn[i2] = a;
    }
}

// ---------------- K2: spike binning  syn = S @ C.T (one-hot), float4 --------
#define BT   32
#define BTH  256
__global__ __launch_bounds__(BTH) void bin_kernel(const float4* __restrict__ Se4,
                                                  const float4* __restrict__ Si4)
{
    __shared__ float be[BT * SUB_NO];
    __shared__ float bi[BT * SUB_NO];
    __shared__ int   ea[E_NO];
    __shared__ int   ia[I_NO];
    const int tid = threadIdx.x;
    const int t0  = blockIdx.x * BT;

    for (int i = tid; i < BT * SUB_NO; i += BTH) { be[i] = 0.0f; bi[i] = 0.0f; }
    for (int i = tid; i < E_NO; i += BTH) ea[i] = g_e_asn[i];
    for (int i = tid; i < I_NO; i += BTH) ia[i] = g_i_asn[i];
    __syncthreads();

    for (int idx = tid; idx < BT * (E_NO/4); idx += BTH) {
        int r = idx / (E_NO/4);
        int c = idx - r * (E_NO/4);
        int t = t0 + r;
        if (t < T_DATA) {
            float4 v = Se4[(size_t)t * (E_NO/4) + c];
            int e0 = c * 4;
            if (v.x != 0.0f) atomicAdd(&be[r * SUB_NO + ea[e0+0]], v.x);
            if (v.y != 0.0f) atomicAdd(&be[r * SUB_NO + ea[e0+1]], v.y);
            if (v.z != 0.0f) atomicAdd(&be[r * SUB_NO + ea[e0+2]], v.z);
            if (v.w != 0.0f) atomicAdd(&be[r * SUB_NO + ea[e0+3]], v.w);
        }
    }
    for (int idx = tid; idx < BT * (I_NO/4); idx += BTH) {
        int r = idx / (I_NO/4);
        int c = idx - r * (I_NO/4);
        int t = t0 + r;
        if (t < T_DATA) {
            float4 v = Si4[(size_t)t * (I_NO/4) + c];
            int i0 = c * 4;
            if (v.x != 0.0f) atomicAdd(&bi[r * SUB_NO + ia[i0+0]], v.x);
            if (v.y != 0.0f) atomicAdd(&bi[r * SUB_NO + ia[i0+1]], v.y);
            if (v.z != 0.0f) atomicAdd(&bi[r * SUB_NO + ia[i0+2]], v.z);
            if (v.w != 0.0f) atomicAdd(&bi[r * SUB_NO + ia[i0+3]], v.w);
        }
    }
    __syncthreads();

    for (int idx = tid; idx < BT * SUB_NO; idx += BTH) {
        int s  = idx / BT;
        int tl = idx - s * BT;
        int t  = t0 + tl;
        if (t < T_DATA) {
            g_syn_e[(size_t)s * T_DATA + t] = be[tl * SUB_NO + s];
            g_syn_i[(size_t)s * T_DATA + t] = bi[tl * SUB_NO + s];
        }
    }
}

// ---------------- K3: IIR for ns (alpha) filters ----------------------------
#define IL    391      // outputs per chunk
#define ICH   512      // chunks per sub (512*391 >= T_DATA)
#define IBC   64       // chunks (= threads) per block
#define IWARM 200
__global__ __launch_bounds__(IBC) void iir_kernel(const float* __restrict__ Wns,
                                                  const float* __restrict__ Tau)
{
    const int s   = blockIdx.y;
    const int cg  = blockIdx.x * IBC;          // first chunk of this block
    const int tid = threadIdx.x;

    float tau_e = Tau[s*2+0] * Tau[s*2+0];
    float tau_i = Tau[s*2+1] * Tau[s*2+1];
    float a_e = 1.0f / tau_e,  a_i = 1.0f / tau_i;
    float r_e = expf(-a_e),    r_i = expf(-a_i);
    float we0 = Wns[s*2+0],    wi0 = Wns[s*2+1];
    float sc_e =  we0 * we0 * a_e;
    float sc_i = -wi0 * wi0 * a_i;

    __shared__ float xe[IBC][33];
    __shared__ float xi[IBC][33];
    __shared__ float yo[IBC][33];

    const float* pe = g_syn_e + (size_t)s * T_DATA;
    const float* pi = g_syn_i + (size_t)s * T_DATA;
    float* po = g_syn_ns + (size_t)s * T_DATA;

    float ue = 0.0f, ve = 0.0f, ui = 0.0f, vi = 0.0f;

    for (int i0 = 0; i0 < 608; i0 += 32) {      // 19 tiles cover 591 steps
        for (int flat = tid; flat < IBC * 32; flat += IBC) {
            int c = flat >> 5, p = flat & 31;
            long t = (long)(cg + c) * IL - IWARM + i0 + p;
            bool ok = (t >= 0) && (t < T_DATA);
            xe[c][p] = ok ? pe[t] : 0.0f;
            xi[c][p] = ok ? pi[t] : 0.0f;
        }
        __syncthreads();

        #pragma unroll
        for (int p = 0; p < 32; p++) {
            float xev = xe[tid][p], xiv = xi[tid][p];
            ve = r_e * (ve + ue);  ue = fmaf(r_e, ue, xev);
            vi = r_i * (vi + ui);  ui = fmaf(r_i, ui, xiv);
            yo[tid][p] = sc_e * ve + sc_i * vi;
        }
        __syncthreads();

        for (int flat = tid; flat < IBC * 32; flat += IBC) {
            int c = flat >> 5, p = flat & 31;
            int io = i0 + p - IWARM;
            long t = (long)(cg + c) * IL + io;
            if (io >= 0 && io < IL && t < T_DATA)
                po[t] = yo[c][p];
        }
    }
}

// ---------------- K4: FIR conv (s kernels, packed f32x2) + hist -------------
// Pair-permuted smem: logical pair q at (q&7)*PG + (q>>3); mainloop pair
// indices are tid*8 + m (m warp-uniform) -> address (m&7)*PG+(m>>3)+tid ->
// lane stride 8B -> conflict-free LDS.64.
// Odd-tap windows are DERIVED from even windows (no shifted smem copy):
//   WO[p] = (WE[p-1].hi, WE[p].lo), p>=1;  WO[0] = (ahead.hi, WE[0].lo)
// where ahead = P[tid*8+99-jj] becomes next iteration's WE[0] (1 LDS/signal/jj).
// Kernel taps (k_e, k_i) are adjacent & 16B-aligned -> LDS.128.
#define CT   2048    // timesteps per block
#define CTH  128     // threads per block (16 outputs = 8 pairs each)
#define NP   8       // pairs per thread
#define XSZ  (CT + T_NO)       // 2248 floats
#define PG   141               // pair groups: 8*141 = 1128 >= 1124 pairs

__device__ __forceinline__ int pidx(int q) { return (q & 7) * PG + (q >> 3); }
__device__ __forceinline__ int paddr(int m, int tid) {
    return (m & 7) * PG + (m >> 3) + tid;
}

__global__ __launch_bounds__(CTH, 5) void conv_kernel(const float* __restrict__ Z)
{
    const int s  = blockIdx.y;
    const int t0 = blockIdx.x * CT;
    __shared__ __align__(16) ull xe[8 * PG];
    __shared__ __align__(16) ull xi[8 * PG];
    __shared__ __align__(16) ull kd[T_NO * 2];
    float* xeF = (float*)xe;
    float* xiF = (float*)xi;
    const int tid = threadIdx.x;

    if (s < SUB_NO) {
        const float* pe = g_syn_e + (size_t)s * T_DATA;
        const float* pi = g_syn_i + (size_t)s * T_DATA;
        for (int i = tid; i < XSZ; i += CTH) {
            int t = t0 - T_NO + i;
            bool ok = (t >= 0) && (t < T_DATA);
            int fi = pidx(i >> 1) * 2 + (i & 1);
            xeF[fi] = ok ? pe[t] : 0.0f;
            xiF[fi] = ok ? pi[t] : 0.0f;
        }
        for (int i = tid; i < T_NO * 2; i += CTH)
            kd[i] = g_kds[(size_t)s * T_NO * 2 + i];
        __syncthreads();

        ull WEe[NP], WOe[NP], WEi[NP], WOi[NP], as2[NP];
        ull ahe = xe[paddr(99, tid)];
        ull ahi = xi[paddr(99, tid)];
        #pragma unroll
        for (int p = 0; p < NP; p++) {
            int a = paddr(100 + p, tid);
            WEe[p] = xe[a]; WEi[p] = xi[a];
            as2[p] = 0ULL;
        }
        WOe[0] = mix_hl(ahe, WEe[0]);
        WOi[0] = mix_hl(ahi, WEi[0]);
        #pragma unroll
        for (int p = 1; p < NP; p++) {
            WOe[p] = mix_hl(WEe[p-1], WEe[p]);
            WOi[p] = mix_hl(WEi[p-1], WEi[p]);
        }

        auto phases = [&](int jj) {
            ulonglong2 k0 = *(const ulonglong2*)&kd[4*jj];      // taps 2jj
            #pragma unroll
            for (int p = 0; p < NP; p++) {
                as2[p] = fma2(k0.x, WEe[p], as2[p]);
                as2[p] = fma2(k0.y, WEi[p], as2[p]);
            }
            ulonglong2 k1 = *(const ulonglong2*)&kd[4*jj + 2];  // taps 2jj+1
            #pragma unroll
            for (int p = 0; p < NP; p++) {
                as2[p] = fma2(k1.x, WOe[p], as2[p]);
                as2[p] = fma2(k1.y, WOi[p], as2[p]);
            }
        };
        auto rot = [&](int jj) {
            #pragma unroll
            for (int p = NP - 1; p > 0; p--) {
                WEe[p] = WEe[p-1]; WOe[p] = WOe[p-1];
                WEi[p] = WEi[p-1]; WOi[p] = WOi[p-1];
            }
            WEe[0] = ahe; WEi[0] = ahi;
            int a = paddr(99 - jj, tid);
            ahe = xe[a]; ahi = xi[a];
            WOe[0] = mix_hl(ahe, WEe[0]);
            WOi[0] = mix_hl(ahi, WEi[0]);
        };

        phases(0);
        #pragma unroll 8
        for (int jj = 1; jj < 97; jj++) { rot(jj); phases(jj); }   // 96 iters
        #pragma unroll
        for (int jj = 97; jj < 100; jj++) { rot(jj); phases(jj); } // tail

        float* os = g_syn_s + (size_t)s * T_DATA + t0 + tid * 16;
        #pragma unroll
        for (int p = 0; p < NP; p++)
            if (t0 + tid * 16 + 2*p < T_DATA) *(ull*)(os + 2*p) = as2[p];
    } else {
        // ---- spike-history slice: hist[t] = sum_j k[j] * Z[t-1-j] ----
        // xe[i] <-> Z[t0 - T_NO - 1 + i]; same window indexing as main path.
        for (int i = tid; i < XSZ; i += CTH) {
            int t = t0 - T_NO - 1 + i;
            int fi = pidx(i >> 1) * 2 + (i & 1);
            xeF[fi] = (t >= 0 && t < T_DATA) ? Z[t] : 0.0f;
        }
        for (int i = tid; i < T_NO * 2; i += CTH) kd[i] = g_hd[i];
        __syncthreads();

        ull WE[NP], WO[NP], hn[NP], hs[NP];
        ull ah = xe[paddr(99, tid)];
        #pragma unroll
        for (int p = 0; p < NP; p++) {
            WE[p] = xe[paddr(100 + p, tid)];
            hn[p] = 0ULL; hs[p] = 0ULL;
        }
        WO[0] = mix_hl(ah, WE[0]);
        #pragma unroll
        for (int p = 1; p < NP; p++) WO[p] = mix_hl(WE[p-1], WE[p]);

        auto phases = [&](int jj) {
            ulonglong2 k0 = *(const ulonglong2*)&kd[4*jj];      // (kn, ks) tap 2jj
            #pragma unroll
            for (int p = 0; p < NP; p++) {
                hn[p] = fma2(k0.x, WE[p], hn[p]);
                hs[p] = fma2(k0.y, WE[p], hs[p]);
            }
            ulonglong2 k1 = *(const ulonglong2*)&kd[4*jj + 2];  // tap 2jj+1
            #pragma unroll
            for (int p = 0; p < NP; p++) {
                hn[p] = fma2(k1.x, WO[p], hn[p]);
                hs[p] = fma2(k1.y, WO[p], hs[p]);
            }
        };
        auto rot = [&](int jj) {
            #pragma unroll
            for (int p = NP - 1; p > 0; p--) { WE[p] = WE[p-1]; WO[p] = WO[p-1]; }
            WE[0] = ah;
            ah = xe[paddr(99 - jj, tid)];
            WO[0] = mix_hl(ah, WE[0]);
        };
        phases(0);
        #pragma unroll 8
        for (int jj = 1; jj < 97; jj++) { rot(jj); phases(jj); }
        #pragma unroll
        for (int jj = 97; jj < 100; jj++) { rot(jj); phases(jj); }

        #pragma unroll
        for (int p = 0; p < NP; p++) {
            int t = t0 + tid * 16 + 2*p;
            if (t < T_DATA) {
                *(ull*)(g_hist_ns + t) = hn[p];
                *(ull*)(g_hist_s  + t) = hs[p];
            }
        }
    }
}

// ---------------- K5: leaf-to-root binary tree + outputs (2 t / thread) -----
#define TTH 128
__global__ __launch_bounds__(TTH) void tree_kernel(
    const float* __restrict__ Theta_ns, const float* __restrict__ Theta_s,
    const float* __restrict__ W_sub_ns, const float* __restrict__ W_sub_s,
    const float* __restrict__ V_o, float* __restrict__ out)
{
    const int gt = blockIdx.x * TTH + threadIdx.x;        // float2 index
    if (gt * 2 >= T_DATA) return;

    float2 vs[SUB_NO], vn[SUB_NO];
    #pragma unroll
    for (int s2 = 0; s2 < SUB_NO; s2++) {
        vs[s2] = ((const float2*)(g_syn_s  + (size_t)s2 * T_DATA))[gt];
        vn[s2] = ((const float2*)(g_syn_ns + (size_t)s2 * T_DATA))[gt];
    }

    #pragma unroll
    for (int idx = SUB_NO - 1; idx >= 1; idx--) {
        const int p = (idx - 1) >> 1;
        float w = __ldg(&W_sub_s[idx]);  float w2s = w * w;
        w = __ldg(&W_sub_ns[idx]);       float w2n = w * w;
        float ts = __ldg(&Theta_s[idx]), tn = __ldg(&Theta_ns[idx]);
        vs[p].x += tanh_ap(vs[idx].x + ts) * w2s;
        vs[p].y += tanh_ap(vs[idx].y + ts) * w2s;
        vn[p].x += tanh_ap(vn[idx].x + tn) * w2n;
        vn[p].y += tanh_ap(vn[idx].y + tn) * w2n;
    }

    float2 hsv = ((const float2*)g_hist_s)[gt];
    float2 hnv = ((const float2*)g_hist_ns)[gt];
    float ts0 = __ldg(&Theta_s[0]), tn0 = __ldg(&Theta_ns[0]);
    float w0 = __ldg(&W_sub_ns[0]); float wn20 = w0 * w0;
    float vo = __ldg(&V_o[0]);

    float2 fv, fz;
    fz.x = 0.5f * tanh_ap(0.5f * (hsv.x + vs[0].x + ts0)) + 0.5f;
    fz.y = 0.5f * tanh_ap(0.5f * (hsv.y + vs[0].y + ts0)) + 0.5f;
    fv.x = tanh_ap(hnv.x + vn[0].x + tn0) * wn20 + vo;
    fv.y = tanh_ap(hnv.y + vn[0].y + tn0) * wn20 + vo;

    ((float2*)out)[gt] = fv;                       // final_V
    ((float2*)(out + T_DATA))[gt] = fz;            // final_Z
}

// ---------------- launch ----------------------------------------------------
extern "C" void kernel_launch(void* const* d_in, const int* in_sizes, int n_in,
                              void* d_out, int out_size)
{
    const float* S_e      = (const float*)d_in[0];
    const float* S_i      = (const float*)d_in[1];
    const float* Z        = (const float*)d_in[2];
    const float* C_syn_e  = (const float*)d_in[4];
    const float* C_syn_i  = (const float*)d_in[5];
    const float* W_syn_ns = (const float*)d_in[6];
    const float* Tau      = (const float*)d_in[7];
    const float* Delta    = (const float*)d_in[8];
    const float* W_syn_s  = (const float*)d_in[9];
    const float* W_sub_ns = (const float*)d_in[10];
    const float* W_sub_s  = (const float*)d_in[11];
    const float* V_o      = (const float*)d_in[12];
    const float* Theta_ns = (const float*)d_in[13];
    const float* Theta_s  = (const float*)d_in[14];
    const float* hist_s_w = (const float*)d_in[15];
    const float* hist_ns_w= (const float*)d_in[16];

    float* out = (float*)d_out;
    float* out_filters = out + 2 * T_DATA;   // final_V | final_Z | filters(82x200)

    setup_kernel<<<40, 128>>>(W_syn_ns, Tau, Delta, W_syn_s, hist_s_w, hist_ns_w,
                              C_syn_e, C_syn_i, out_filters);

    bin_kernel<<<(T_DATA + BT - 1) / BT, BTH>>>((const float4*)S_e,
                                                (const float4*)S_i);

    iir_kernel<<<dim3(ICH / IBC, SUB_NO), IBC>>>(W_syn_ns, Tau);

    dim3 cgrid((T_DATA + CT - 1) / CT, SUB_NO + 1);  // y==SUB_NO -> hist slice
    conv_kernel<<<cgrid, CTH>>>(Z);

    tree_kernel<<<(T_DATA / 2 + TTH - 1) / TTH, TTH>>>(Theta_ns, Theta_s,
                                                       W_sub_ns, W_sub_s, V_o, out);
}

// round 15
// speedup vs baseline: 1.5187x; 1.1408x over previous
#include <cuda_runtime.h>
#include <math.h>

#define T_DATA 200000
#define SUB_NO 20
#define T_NO   200
#define E_NO   400
#define I_NO   100
#define N_BASIS 20

typedef unsigned long long ull;

// ---------------- packed f32x2 helpers --------------------------------------
__device__ __forceinline__ ull fma2(ull a, ull b, ull c) {
    ull d;
    asm("fma.rn.f32x2 %0, %1, %2, %3;" : "=l"(d) : "l"(a), "l"(b), "l"(c));
    return d;
}
__device__ __forceinline__ ull add2(ull a, ull b) {
    ull d;
    asm("add.rn.f32x2 %0, %1, %2;" : "=l"(d) : "l"(a), "l"(b));
    return d;
}
__device__ __forceinline__ ull pk2(float lo, float hi) {
    ull r;
    asm("mov.b64 %0, {%1, %2};" : "=l"(r) : "f"(lo), "f"(hi));
    return r;
}
// result: lo32 = hi32(a), hi32 = lo32(b)
__device__ __forceinline__ ull mix_hl(ull a, ull b) {
    unsigned int ah = (unsigned int)(a >> 32);
    unsigned int bl = (unsigned int)b;
    ull r;
    asm("mov.b64 %0, {%1, %2};" : "=l"(r) : "r"(ah), "r"(bl));
    return r;
}
__device__ __forceinline__ float tanh_ap(float x) {
    float y;
    asm("tanh.approx.f32 %0, %1;" : "=f"(y) : "f"(x));
    return y;
}

// ---------------- scratch (device globals; no allocations allowed) ----------
__device__ float  g_syn_e [SUB_NO * T_DATA];
__device__ float  g_syn_i [SUB_NO * T_DATA];
__device__ float  g_syn_ns[SUB_NO * T_DATA];   // from IIR
__device__ float  g_syn_s [SUB_NO * T_DATA];   // from FIR
__device__ float  g_hist_ns[T_DATA];
__device__ float  g_hist_s [T_DATA];
__device__ ull    g_kds[SUB_NO * T_NO * 2];    // duplicated (k,k) pairs {e_s, i_s}
__device__ ull    g_hd[T_NO * 2];              // duplicated hist kernels {ns, s}
__device__ int    g_e_asn[E_NO];
__device__ int    g_i_asn[I_NO];

// ---------------- K1: filters, assignments (multi-block) --------------------
__global__ void setup_kernel(const float* __restrict__ Wns,
                             const float* __restrict__ Tau,
                             const float* __restrict__ Delta,
                             const float* __restrict__ Wsyn_s,
                             const float* __restrict__ hist_s_w,
                             const float* __restrict__ hist_ns_w,
                             const float* __restrict__ C_syn_e,
                             const float* __restrict__ C_syn_i,
                             float* __restrict__ out_filters)
{
    const float PI_F = 3.14159265358979323846f;
    const int gtid = blockIdx.x * blockDim.x + threadIdx.x;
    const int gstr = gridDim.x * blockDim.x;

    for (int idx = gtid; idx < SUB_NO * T_NO; idx += gstr) {
        int s = idx / T_NO;
        int j = idx - s * T_NO;
        float t = (float)j;
        float tau_e = Tau[s*2+0] * Tau[s*2+0];
        float tau_i = Tau[s*2+1] * Tau[s*2+1];
        float te = fmaxf(t - Delta[s*2+0], 0.0f) / tau_e;
        float ti = fmaxf(t - Delta[s*2+1], 0.0f) / tau_i;
        float we0 = Wns[s*2+0], wi0 = Wns[s*2+1];
        float ke =  te * expf(-te) * we0 * we0;
        float ki = -ti * expf(-ti) * wi0 * wi0;

        float raw = 5.0f * logf(t + 1.0f);
        float se = 0.0f, si = 0.0f;
        #pragma unroll
        for (int b = 0; b < N_BASIS; b++) {
            float phi = 1.57079632679489662f * (float)b;
            float v = 0.0f;
            if (raw >= phi - PI_F && raw <= phi + PI_F)
                v = 0.5f * cosf(raw - phi) + 0.5f;
            float wse = Wsyn_s[(s*N_BASIS + b)*2 + 0];
            float wsi = Wsyn_s[(s*N_BASIS + b)*2 + 1];
            se += wse * wse * v;
            si += wsi * wsi * v;
        }
        si = -si;

        g_kds[idx*2 + 0] = pk2(se, se);
        g_kds[idx*2 + 1] = pk2(si, si);
        out_filters[0*SUB_NO*T_NO + idx] = ke;
        out_filters[1*SUB_NO*T_NO + idx] = ki;
        out_filters[2*SUB_NO*T_NO + idx] = se;
        out_filters[3*SUB_NO*T_NO + idx] = si;
    }

    for (int j = gtid; j < T_NO; j += gstr) {
        float raw = 5.0f * logf((float)j + 1.0f);
        float hs = 0.0f, hns = 0.0f;
        #pragma unroll
        for (int b = 0; b < N_BASIS; b++) {
            float phi = 1.57079632679489662f * (float)b;
            float v = 0.0f;
            if (raw >= phi - PI_F && raw <= phi + PI_F)
                v = 0.5f * cosf(raw - phi) + 0.5f;
            hs  += hist_s_w[b]  * v;
            hns += hist_ns_w[b] * v;
        }
        g_hd[j*2 + 0] = pk2(hns, hns);
        g_hd[j*2 + 1] = pk2(hs, hs);
        out_filters[4*SUB_NO*T_NO + j]        = hns;  // row 80
        out_filters[4*SUB_NO*T_NO + T_NO + j] = hs;   // row 81
    }

    for (int e = gtid; e < E_NO; e += gstr) {
        int a = 0;
        for (int s = 0; s < SUB_NO; s++)
            if (C_syn_e[s*E_NO + e] != 0.0f) a = s;
        g_e_asn[e] = a;
    }
    for (int i2 = gtid; i2 < I_NO; i2 += gstr) {
        int a = 0;
        for (int s = 0; s < SUB_NO; s++)
            if (C_syn_i[s*I_NO + i2] != 0.0f) a = s;
        g_i_asn[i2] = a;
    }
}

// ---------------- K2: spike binning  syn = S @ C.T (one-hot), float4 --------
#define BT   32
#define BTH  256
__global__ __launch_bounds__(BTH) void bin_kernel(const float4* __restrict__ Se4,
                                                  const float4* __restrict__ Si4)
{
    __shared__ float be[BT * SUB_NO];
    __shared__ float bi[BT * SUB_NO];
    __shared__ int   ea[E_NO];
    __shared__ int   ia[I_NO];
    const int tid = threadIdx.x;
    const int t0  = blockIdx.x * BT;

    for (int i = tid; i < BT * SUB_NO; i += BTH) { be[i] = 0.0f; bi[i] = 0.0f; }
    for (int i = tid; i < E_NO; i += BTH) ea[i] = g_e_asn[i];
    for (int i = tid; i < I_NO; i += BTH) ia[i] = g_i_asn[i];
    __syncthreads();

    for (int idx = tid; idx < BT * (E_NO/4); idx += BTH) {
        int r = idx / (E_NO/4);
        int c = idx - r * (E_NO/4);
        int t = t0 + r;
        if (t < T_DATA) {
            float4 v = Se4[(size_t)t * (E_NO/4) + c];
            int e0 = c * 4;
            if (v.x != 0.0f) atomicAdd(&be[r * SUB_NO + ea[e0+0]], v.x);
            if (v.y != 0.0f) atomicAdd(&be[r * SUB_NO + ea[e0+1]], v.y);
            if (v.z != 0.0f) atomicAdd(&be[r * SUB_NO + ea[e0+2]], v.z);
            if (v.w != 0.0f) atomicAdd(&be[r * SUB_NO + ea[e0+3]], v.w);
        }
    }
    for (int idx = tid; idx < BT * (I_NO/4); idx += BTH) {
        int r = idx / (I_NO/4);
        int c = idx - r * (I_NO/4);
        int t = t0 + r;
        if (t < T_DATA) {
            float4 v = Si4[(size_t)t * (I_NO/4) + c];
            int i0 = c * 4;
            if (v.x != 0.0f) atomicAdd(&bi[r * SUB_NO + ia[i0+0]], v.x);
            if (v.y != 0.0f) atomicAdd(&bi[r * SUB_NO + ia[i0+1]], v.y);
            if (v.z != 0.0f) atomicAdd(&bi[r * SUB_NO + ia[i0+2]], v.z);
            if (v.w != 0.0f) atomicAdd(&bi[r * SUB_NO + ia[i0+3]], v.w);
        }
    }
    __syncthreads();

    for (int idx = tid; idx < BT * SUB_NO; idx += BTH) {
        int s  = idx / BT;
        int tl = idx - s * BT;
        int t  = t0 + tl;
        if (t < T_DATA) {
            g_syn_e[(size_t)s * T_DATA + t] = be[tl * SUB_NO + s];
            g_syn_i[(size_t)s * T_DATA + t] = bi[tl * SUB_NO + s];
        }
    }
}

// ---------------- K3: IIR for ns (alpha) filters ----------------------------
// Shorter chunks than round 14: halves the serial chain, doubles warps.
#define IL    196      // outputs per chunk
#define ICH   1024     // chunks per sub (1024*196 = 200704 >= T_DATA)
#define IBC   64       // chunks (= threads) per block
#define IWARM 200
#define ITILES_END 416 // 13 tiles of 32 cover IWARM+IL = 396 steps
__global__ __launch_bounds__(IBC) void iir_kernel(const float* __restrict__ Wns,
                                                  const float* __restrict__ Tau)
{
    const int s   = blockIdx.y;
    const int cg  = blockIdx.x * IBC;          // first chunk of this block
    const int tid = threadIdx.x;

    float tau_e = Tau[s*2+0] * Tau[s*2+0];
    float tau_i = Tau[s*2+1] * Tau[s*2+1];
    float a_e = 1.0f / tau_e,  a_i = 1.0f / tau_i;
    float r_e = expf(-a_e),    r_i = expf(-a_i);
    float we0 = Wns[s*2+0],    wi0 = Wns[s*2+1];
    float sc_e =  we0 * we0 * a_e;
    float sc_i = -wi0 * wi0 * a_i;

    __shared__ float xe[IBC][33];
    __shared__ float xi[IBC][33];
    __shared__ float yo[IBC][33];

    const float* pe = g_syn_e + (size_t)s * T_DATA;
    const float* pi = g_syn_i + (size_t)s * T_DATA;
    float* po = g_syn_ns + (size_t)s * T_DATA;

    float ue = 0.0f, ve = 0.0f, ui = 0.0f, vi = 0.0f;

    for (int i0 = 0; i0 < ITILES_END; i0 += 32) {
        for (int flat = tid; flat < IBC * 32; flat += IBC) {
            int c = flat >> 5, p = flat & 31;
            long t = (long)(cg + c) * IL - IWARM + i0 + p;
            bool ok = (t >= 0) && (t < T_DATA);
            xe[c][p] = ok ? pe[t] : 0.0f;
            xi[c][p] = ok ? pi[t] : 0.0f;
        }
        __syncthreads();

        #pragma unroll
        for (int p = 0; p < 32; p++) {
            float xev = xe[tid][p], xiv = xi[tid][p];
            ve = r_e * (ve + ue);  ue = fmaf(r_e, ue, xev);
            vi = r_i * (vi + ui);  ui = fmaf(r_i, ui, xiv);
            yo[tid][p] = sc_e * ve + sc_i * vi;
        }
        __syncthreads();

        for (int flat = tid; flat < IBC * 32; flat += IBC) {
            int c = flat >> 5, p = flat & 31;
            int io = i0 + p - IWARM;
            long t = (long)(cg + c) * IL + io;
            if (io >= 0 && io < IL && t < T_DATA)
                po[t] = yo[c][p];
        }
    }
}

// ---------------- K4: FIR conv (s kernels, packed f32x2) + hist -------------
// Pair-permuted smem: logical pair q at (q&7)*PG + (q>>3); warp-uniform m in
// q = tid*8 + m -> address (m&7)*PG+(m>>3)+tid -> conflict-free LDS.64.
// DUAL-ACCUMULATOR scheme (no odd windows, no per-tap mixes):
//   A[p] += k[2jj]   * WE[p]   (even taps)
//   B[p] += k[2jj-1] * WE[p]   (odd tap 2jj-1 shares window jj!)
//   B[NP] uses the register evicted from the rotation top (free).
// Final: out[p] = A[p] + (B[p].hi, B[p+1].lo)  -- one mix per pair, at end.
#define CT   2048    // timesteps per block
#define CTH  128     // threads per block (16 outputs = 8 pairs each)
#define NP   8       // pairs per thread
#define XSZ  (CT + T_NO)       // 2248 floats
#define PG   141               // pair groups: 8*141 = 1128 >= 1124 pairs

__device__ __forceinline__ int pidx(int q) { return (q & 7) * PG + (q >> 3); }
__device__ __forceinline__ int paddr(int m, int tid) {
    return (m & 7) * PG + (m >> 3) + tid;
}

__global__ __launch_bounds__(CTH, 5) void conv_kernel(const float* __restrict__ Z)
{
    const int s  = blockIdx.y;
    const int t0 = blockIdx.x * CT;
    __shared__ __align__(16) ull xe[8 * PG];
    __shared__ __align__(16) ull xi[8 * PG];
    __shared__ __align__(16) ull kd[T_NO * 2];
    float* xeF = (float*)xe;
    float* xiF = (float*)xi;
    const int tid = threadIdx.x;

    if (s < SUB_NO) {
        const float* pe = g_syn_e + (size_t)s * T_DATA;
        const float* pi = g_syn_i + (size_t)s * T_DATA;
        for (int i = tid; i < XSZ; i += CTH) {
            int t = t0 - T_NO + i;
            bool ok = (t >= 0) && (t < T_DATA);
            int fi = pidx(i >> 1) * 2 + (i & 1);
            xeF[fi] = ok ? pe[t] : 0.0f;
            xiF[fi] = ok ? pi[t] : 0.0f;
        }
        for (int i = tid; i < T_NO * 2; i += CTH)
            kd[i] = g_kds[(size_t)s * T_NO * 2 + i];
        __syncthreads();

        ull WEe[NP], WEi[NP], as2[NP], bs[NP + 1];
        ull ahe, ahi, tope, topi;
        ahe = xe[paddr(99, tid)];
        ahi = xi[paddr(99, tid)];
        #pragma unroll
        for (int p = 0; p < NP; p++) {
            int a = paddr(100 + p, tid);
            WEe[p] = xe[a]; WEi[p] = xi[a];
            as2[p] = 0ULL;  bs[p] = 0ULL;
        }
        bs[NP] = 0ULL;
        tope = WEe[NP - 1]; topi = WEi[NP - 1];   // init (used from jj=1)

        auto phaseA = [&](int jj) {               // tap 2jj on current windows
            ulonglong2 kA = *(const ulonglong2*)&kd[4*jj];
            #pragma unroll
            for (int p = 0; p < NP; p++) {
                as2[p] = fma2(kA.x, WEe[p], as2[p]);
                as2[p] = fma2(kA.y, WEi[p], as2[p]);
            }
        };
        auto phaseB = [&](int jj) {               // tap 2jj-1 on current windows
            ulonglong2 kB = *(const ulonglong2*)&kd[4*jj - 2];
            #pragma unroll
            for (int p = 0; p < NP; p++) {
                bs[p] = fma2(kB.x, WEe[p], bs[p]);
                bs[p] = fma2(kB.y, WEi[p], bs[p]);
            }
            bs[NP] = fma2(kB.x, tope, bs[NP]);
            bs[NP] = fma2(kB.y, topi, bs[NP]);
        };
        auto rot = [&](int jj) {
            tope = WEe[NP - 1]; topi = WEi[NP - 1];
            #pragma unroll
            for (int p = NP - 1; p > 0; p--) { WEe[p] = WEe[p-1]; WEi[p] = WEi[p-1]; }
            WEe[0] = ahe; WEi[0] = ahi;
            int a = paddr(99 - jj, tid);
            ahe = xe[a]; ahi = xi[a];
        };

        phaseA(0);
        #pragma unroll 8
        for (int jj = 1; jj < 97; jj++) { rot(jj); phaseB(jj); phaseA(jj); }
        #pragma unroll
        for (int jj = 97; jj < 100; jj++) { rot(jj); phaseB(jj); phaseA(jj); }
        { // jj = 100: odd tap 199 only
            rot(100);
            phaseB(100);
        }

        float* os = g_syn_s + (size_t)s * T_DATA + t0 + tid * 16;
        #pragma unroll
        for (int p = 0; p < NP; p++) {
            if (t0 + tid * 16 + 2*p < T_DATA) {
                ull o = add2(as2[p], mix_hl(bs[p], bs[p+1]));
                *(ull*)(os + 2*p) = o;
            }
        }
    } else {
        // ---- spike-history slice: hist[t] = sum_j k[j] * Z[t-1-j] ----
        for (int i = tid; i < XSZ; i += CTH) {
            int t = t0 - T_NO - 1 + i;
            int fi = pidx(i >> 1) * 2 + (i & 1);
            xeF[fi] = (t >= 0 && t < T_DATA) ? Z[t] : 0.0f;
        }
        for (int i = tid; i < T_NO * 2; i += CTH) kd[i] = g_hd[i];
        __syncthreads();

        ull WE[NP], an[NP], as_[NP], bn[NP + 1], bsx[NP + 1];
        ull ah, top;
        ah = xe[paddr(99, tid)];
        #pragma unroll
        for (int p = 0; p < NP; p++) {
            WE[p] = xe[paddr(100 + p, tid)];
            an[p] = 0ULL; as_[p] = 0ULL; bn[p] = 0ULL; bsx[p] = 0ULL;
        }
        bn[NP] = 0ULL; bsx[NP] = 0ULL;
        top = WE[NP - 1];

        auto phaseA = [&](int jj) {
            ulonglong2 kA = *(const ulonglong2*)&kd[4*jj];      // (kn, ks) tap 2jj
            #pragma unroll
            for (int p = 0; p < NP; p++) {
                an[p]  = fma2(kA.x, WE[p], an[p]);
                as_[p] = fma2(kA.y, WE[p], as_[p]);
            }
        };
        auto phaseB = [&](int jj) {
            ulonglong2 kB = *(const ulonglong2*)&kd[4*jj - 2];  // tap 2jj-1
            #pragma unroll
            for (int p = 0; p < NP; p++) {
                bn[p]  = fma2(kB.x, WE[p], bn[p]);
                bsx[p] = fma2(kB.y, WE[p], bsx[p]);
            }
            bn[NP]  = fma2(kB.x, top, bn[NP]);
            bsx[NP] = fma2(kB.y, top, bsx[NP]);
        };
        auto rot = [&](int jj) {
            top = WE[NP - 1];
            #pragma unroll
            for (int p = NP - 1; p > 0; p--) WE[p] = WE[p-1];
            WE[0] = ah;
            ah = xe[paddr(99 - jj, tid)];
        };

        phaseA(0);
        #pragma unroll 8
        for (int jj = 1; jj < 97; jj++) { rot(jj); phaseB(jj); phaseA(jj); }
        #pragma unroll
        for (int jj = 97; jj < 100; jj++) { rot(jj); phaseB(jj); phaseA(jj); }
        { rot(100); phaseB(100); }

        #pragma unroll
        for (int p = 0; p < NP; p++) {
            int t = t0 + tid * 16 + 2*p;
            if (t < T_DATA) {
                *(ull*)(g_hist_ns + t) = add2(an[p],  mix_hl(bn[p],  bn[p+1]));
                *(ull*)(g_hist_s  + t) = add2(as_[p], mix_hl(bsx[p], bsx[p+1]));
            }
        }
    }
}

// ---------------- K5: leaf-to-root binary tree + outputs (2 t / thread) -----
#define TTH 128
__global__ __launch_bounds__(TTH) void tree_kernel(
    const float* __restrict__ Theta_ns, const float* __restrict__ Theta_s,
    const float* __restrict__ W_sub_ns, const float* __restrict__ W_sub_s,
    const float* __restrict__ V_o, float* __restrict__ out)
{
    const int gt = blockIdx.x * TTH + threadIdx.x;        // float2 index
    if (gt * 2 >= T_DATA) return;

    float2 vs[SUB_NO], vn[SUB_NO];
    #pragma unroll
    for (int s2 = 0; s2 < SUB_NO; s2++) {
        vs[s2] = ((const float2*)(g_syn_s  + (size_t)s2 * T_DATA))[gt];
        vn[s2] = ((const float2*)(g_syn_ns + (size_t)s2 * T_DATA))[gt];
    }

    #pragma unroll
    for (int idx = SUB_NO - 1; idx >= 1; idx--) {
        const int p = (idx - 1) >> 1;
        float w = __ldg(&W_sub_s[idx]);  float w2s = w * w;
        w = __ldg(&W_sub_ns[idx]);       float w2n = w * w;
        float ts = __ldg(&Theta_s[idx]), tn = __ldg(&Theta_ns[idx]);
        vs[p].x += tanh_ap(vs[idx].x + ts) * w2s;
        vs[p].y += tanh_ap(vs[idx].y + ts) * w2s;
        vn[p].x += tanh_ap(vn[idx].x + tn) * w2n;
        vn[p].y += tanh_ap(vn[idx].y + tn) * w2n;
    }

    float2 hsv = ((const float2*)g_hist_s)[gt];
    float2 hnv = ((const float2*)g_hist_ns)[gt];
    float ts0 = __ldg(&Theta_s[0]), tn0 = __ldg(&Theta_ns[0]);
    float w0 = __ldg(&W_sub_ns[0]); float wn20 = w0 * w0;
    float vo = __ldg(&V_o[0]);

    float2 fv, fz;
    fz.x = 0.5f * tanh_ap(0.5f * (hsv.x + vs[0].x + ts0)) + 0.5f;
    fz.y = 0.5f * tanh_ap(0.5f * (hsv.y + vs[0].y + ts0)) + 0.5f;
    fv.x = tanh_ap(hnv.x + vn[0].x + tn0) * wn20 + vo;
    fv.y = tanh_ap(hnv.y + vn[0].y + tn0) * wn20 + vo;

    ((float2*)out)[gt] = fv;                       // final_V
    ((float2*)(out + T_DATA))[gt] = fz;            // final_Z
}

// ---------------- launch ----------------------------------------------------
extern "C" void kernel_launch(void* const* d_in, const int* in_sizes, int n_in,
                              void* d_out, int out_size)
{
    const float* S_e      = (const float*)d_in[0];
    const float* S_i      = (const float*)d_in[1];
    const float* Z        = (const float*)d_in[2];
    const float* C_syn_e  = (const float*)d_in[4];
    const float* C_syn_i  = (const float*)d_in[5];
    const float* W_syn_ns = (const float*)d_in[6];
    const float* Tau      = (const float*)d_in[7];
    const float* Delta    = (const float*)d_in[8];
    const float* W_syn_s  = (const float*)d_in[9];
    const float* W_sub_ns = (const float*)d_in[10];
    const float* W_sub_s  = (const float*)d_in[11];
    const float* V_o      = (const float*)d_in[12];
    const float* Theta_ns = (const float*)d_in[13];
    const float* Theta_s  = (const float*)d_in[14];
    const float* hist_s_w = (const float*)d_in[15];
    const float* hist_ns_w= (const float*)d_in[16];

    float* out = (float*)d_out;
    float* out_filters = out + 2 * T_DATA;   // final_V | final_Z | filters(82x200)

    setup_kernel<<<40, 128>>>(W_syn_ns, Tau, Delta, W_syn_s, hist_s_w, hist_ns_w,
                              C_syn_e, C_syn_i, out_filters);

    bin_kernel<<<(T_DATA + BT - 1) / BT, BTH>>>((const float4*)S_e,
                                                (const float4*)S_i);

    iir_kernel<<<dim3(ICH / IBC, SUB_NO), IBC>>>(W_syn_ns, Tau);

    dim3 cgrid((T_DATA + CT - 1) / CT, SUB_NO + 1);  // y==SUB_NO -> hist slice
    conv_kernel<<<cgrid, CTH>>>(Z);

    tree_kernel<<<(T_DATA / 2 + TTH - 1) / TTH, TTH>>>(Theta_ns, Theta_s,
                                                       W_sub_ns, W_sub_s, V_o, out);
}